// round 4
// baseline (speedup 1.0000x reference)
#include <cuda_runtime.h>
#include <cuda_bf16.h>

#define EPS 1e-9f

static constexpr int BMAX = 1024;
static constexpr int DMAX = 512;
static constexpr int UMAX = 512;

// Scratch (device globals — no allocation allowed)
__device__ float2 g_LN [BMAX * DMAX];   // {log2|x+eps|, neg?1:0}
__device__ float4 g_PWD[DMAX * UMAX];   // {p, w, odd?-2w:0, 0}  -> one LDG.128

// ---------------- Fused prepass ----------------
__global__ void prep_kernel(const float* __restrict__ x,
                            const float* __restrict__ w,
                            const float* __restrict__ p,
                            int nLN, int nDW) {
    int i = blockIdx.x * blockDim.x + threadIdx.x;
    if (i < nLN) {
        float xe = x[i] + EPS;
        g_LN[i] = make_float2(log2f(fabsf(xe)), (xe < 0.f) ? 1.f : 0.f);
    }
    if (i < nDW) {
        float pv = p[i];
        float wv = w[i];
        float dw = (fmodf(pv, 2.f) != 0.f) ? (-2.f * wv) : 0.f;
        g_PWD[i] = make_float4(pv, wv, dw, 0.f);
    }
}

// ---------------- Main kernel ----------------
// 128 threads, upt=1, TBT=2 b-rows, DC=4 d-chunk.
// LDG per chunk per thread: 4x LDG.128 (pwd) + 2x LDG.128 (ln) = 6 per 8 elems.
static constexpr int DC      = 4;
static constexpr int TBT     = 2;
static constexpr int THREADS = 128;

__global__ __launch_bounds__(THREADS, 12)
void power_layer_kernel(const float* __restrict__ bias,
                        float* __restrict__ out,
                        int D, int U) {
    const int u  = blockIdx.y * THREADS + threadIdx.x;
    const int b0 = blockIdx.x * TBT;

    float acc[TBT];
#pragma unroll
    for (int bb = 0; bb < TBT; bb++) acc[bb] = 0.f;

    for (int d0 = 0; d0 < D; d0 += DC) {
        float4 pwd[DC];
#pragma unroll
        for (int j = 0; j < DC; j++)
            pwd[j] = g_PWD[(d0 + j) * U + u];      // {p, w, dw, _}

#pragma unroll
        for (int bb = 0; bb < TBT; bb++) {
            // warp-uniform -> L1 broadcast; float4 = 2 x {log2, flag}
            const float4* __restrict__ ln4 =
                (const float4*)(g_LN + (size_t)(b0 + bb) * D + d0);
            float4 lnv[DC / 2];
#pragma unroll
            for (int q = 0; q < DC / 2; q++) lnv[q] = ln4[q];

#pragma unroll
            for (int j = 0; j < DC; j++) {
                const float lv = (j & 1) ? lnv[j >> 1].z : lnv[j >> 1].x;
                const float fl = (j & 1) ? lnv[j >> 1].w : lnv[j >> 1].y;

                float e = pwd[j].x * lv;                     // FMUL
                float v;
                asm("ex2.approx.f32 %0, %1;" : "=f"(v) : "f"(e));  // MUFU
                float ws = fmaf(fl, pwd[j].z, pwd[j].y);     // FFMA (signed w)
                acc[bb]  = fmaf(ws, v, acc[bb]);             // FFMA
            }
        }
    }

    const float bv = bias[u];
#pragma unroll
    for (int bb = 0; bb < TBT; bb++)
        out[(size_t)(b0 + bb) * U + u] = acc[bb] + bv;
}

// ---------------- Launch ----------------
extern "C" void kernel_launch(void* const* d_in, const int* in_sizes, int n_in,
                              void* d_out, int out_size) {
    const float* x    = (const float*)d_in[0];
    const float* w    = (const float*)d_in[1];
    const float* p    = (const float*)d_in[2];
    const float* bias = (const float*)d_in[3];
    float* out        = (float*)d_out;

    const int U = in_sizes[3];            // 512
    const int D = in_sizes[1] / U;        // 512
    const int B = in_sizes[0] / D;        // 1024

    const int nLN = B * D;                // 524288
    const int nDW = D * U;                // 262144
    const int nmax = nLN > nDW ? nLN : nDW;
    prep_kernel<<<(nmax + 255) / 256, 256>>>(x, w, p, nLN, nDW);

    dim3 grid(B / TBT, U / THREADS);      // (512, 4) = 2048 blocks x 4 warps
    power_layer_kernel<<<grid, THREADS>>>(bias, out, D, U);
}

// round 5
// speedup vs baseline: 2.2564x; 2.2564x over previous
#include <cuda_runtime.h>
#include <cuda_bf16.h>

#define EPS 1e-9f

static constexpr int BMAX = 1024;
static constexpr int DMAX = 512;
static constexpr int UMAX = 512;

// Scratch (device globals — no allocation allowed)
__device__ float2       g_LN[BMAX * DMAX];   // {log2|x+eps|, bitcast(neg ? 0xFFFFFFFF : 0)}
__device__ float2       g_PW[DMAX * UMAX];   // {p, w}
__device__ unsigned int g_OM[DMAX * UMAX];   // odd(p) ? 0x80000000 : 0

// ---------------- Fused prepass (also zero-inits out) ----------------
__global__ void prep_kernel(const float* __restrict__ x,
                            const float* __restrict__ w,
                            const float* __restrict__ p,
                            float* __restrict__ out,
                            int nLN, int nDW, int nOut) {
    int i = blockIdx.x * blockDim.x + threadIdx.x;
    if (i < nLN) {
        float xe = x[i] + EPS;
        float2 v;
        v.x = log2f(fabsf(xe));
        v.y = __uint_as_float((xe < 0.f) ? 0xFFFFFFFFu : 0u);
        g_LN[i] = v;
    }
    if (i < nDW) {
        float pv = p[i];
        g_PW[i] = make_float2(pv, w[i]);
        g_OM[i] = (fmodf(pv, 2.f) != 0.f) ? 0x80000000u : 0u;
    }
    if (i < nOut) out[i] = 0.f;
}

// ---------------- Main kernel ----------------
// upt=1, TBT=8 b-rows, DC=4 d-chunk, 2-way split over D with atomicAdd finish.
// Per elem: FMUL (e=p*l), MUFU (ex2), LOP3 (conditional sign flip), FFMA (acc).
static constexpr int DC      = 4;
static constexpr int TBT     = 8;
static constexpr int THREADS = 128;
static constexpr int DSPLIT  = 2;

__global__ __launch_bounds__(THREADS, 8)
void power_layer_kernel(const float* __restrict__ bias,
                        float* __restrict__ out,
                        int D, int U) {
    const int u    = blockIdx.y * THREADS + threadIdx.x;
    const int b0   = blockIdx.x * TBT;
    const int dz   = blockIdx.z;
    const int dlo  = dz * (D / DSPLIT);
    const int dhi  = dlo + (D / DSPLIT);

    float acc[TBT];
#pragma unroll
    for (int bb = 0; bb < TBT; bb++) acc[bb] = 0.f;

    for (int d0 = dlo; d0 < dhi; d0 += DC) {
        // per-(d,u): {p,w} via LDG.64 (2 wf), mask via LDG.32 (1 wf)
        float2       pw[DC];
        unsigned int om[DC];
#pragma unroll
        for (int j = 0; j < DC; j++) {
            int r = (d0 + j) * U + u;
            pw[j] = g_PW[r];
            om[j] = g_OM[r];
        }

#pragma unroll
        for (int bb = 0; bb < TBT; bb++) {
            // warp-uniform -> 1-sector broadcast wavefronts
            const float4* __restrict__ ln4 =
                (const float4*)(g_LN + (size_t)(b0 + bb) * D + d0);
            float4 lnv[DC / 2];
#pragma unroll
            for (int q = 0; q < DC / 2; q++) lnv[q] = ln4[q];

#pragma unroll
            for (int j = 0; j < DC; j++) {
                const float        lv = (j & 1) ? lnv[j >> 1].z : lnv[j >> 1].x;
                const unsigned int nm = __float_as_uint((j & 1) ? lnv[j >> 1].w
                                                                : lnv[j >> 1].y);
                float e = pw[j].x * lv;                              // FMUL
                float v;
                asm("ex2.approx.f32 %0, %1;" : "=f"(v) : "f"(e));    // MUFU
                // flip sign iff odd(p) && x<0 : one LOP3 (v ^ (om & nm))
                v = __uint_as_float(__float_as_uint(v) ^ (om[j] & nm));
                acc[bb] = fmaf(pw[j].y, v, acc[bb]);                 // FFMA
            }
        }
    }

    const float bv = (dz == 0) ? bias[u] : 0.f;
#pragma unroll
    for (int bb = 0; bb < TBT; bb++)
        atomicAdd(&out[(size_t)(b0 + bb) * U + u], acc[bb] + bv);
}

// ---------------- Launch ----------------
extern "C" void kernel_launch(void* const* d_in, const int* in_sizes, int n_in,
                              void* d_out, int out_size) {
    const float* x    = (const float*)d_in[0];
    const float* w    = (const float*)d_in[1];
    const float* p    = (const float*)d_in[2];
    const float* bias = (const float*)d_in[3];
    float* out        = (float*)d_out;

    const int U = in_sizes[3];            // 512
    const int D = in_sizes[1] / U;        // 512
    const int B = in_sizes[0] / D;        // 1024

    const int nLN  = B * D;               // 524288
    const int nDW  = D * U;               // 262144
    const int nOut = out_size;            // 524288
    int nmax = nLN > nDW ? nLN : nDW;
    if (nOut > nmax) nmax = nOut;
    prep_kernel<<<(nmax + 255) / 256, 256>>>(x, w, p, out, nLN, nDW, nOut);

    dim3 grid(B / TBT, U / THREADS, DSPLIT);  // (128, 4, 2) = 1024 blocks x 4 warps
    power_layer_kernel<<<grid, THREADS>>>(bias, out, D, U);
}

// round 6
// speedup vs baseline: 2.5840x; 1.1452x over previous
#include <cuda_runtime.h>
#include <cuda_bf16.h>

#define EPS 1e-9f

static constexpr int BMAX = 1024;
static constexpr int DMAX = 512;
static constexpr int UMAX = 512;

// Scratch (device globals — no allocation allowed)
__device__ float2 g_LN [BMAX * DMAX];       // {log2|x+eps|, bitcast(neg ? 0xFFFFFFFF : 0)}
__device__ float4 g_PW4[DMAX * UMAX / 2];   // per u-pair: {p0, w0, p1, w1}
__device__ uint2  g_OM2[DMAX * UMAX / 2];   // per u-pair: odd(p)?0x80000000:0

// ---------------- Fused prepass (also inits out = bias) ----------------
__global__ void prep_kernel(const float* __restrict__ x,
                            const float* __restrict__ w,
                            const float* __restrict__ p,
                            const float* __restrict__ bias,
                            float* __restrict__ out,
                            int nLN, int nPW, int nOut, int U) {
    int i = blockIdx.x * blockDim.x + threadIdx.x;
    if (i < nLN) {
        float xe = x[i] + EPS;
        float2 v;
        v.x = log2f(fabsf(xe));
        v.y = __uint_as_float((xe < 0.f) ? 0xFFFFFFFFu : 0u);
        g_LN[i] = v;
    }
    if (i < nPW) {
        const int U2 = U >> 1;
        int d  = i / U2;
        int u  = (i - d * U2) * 2;
        int idx = d * U + u;
        float p0 = p[idx],     p1 = p[idx + 1];
        float w0 = w[idx],     w1 = w[idx + 1];
        g_PW4[i] = make_float4(p0, w0, p1, w1);
        uint2 m;
        m.x = (fmodf(p0, 2.f) != 0.f) ? 0x80000000u : 0u;
        m.y = (fmodf(p1, 2.f) != 0.f) ? 0x80000000u : 0u;
        g_OM2[i] = m;
    }
    if (i < nOut) out[i] = bias[i & (U - 1)];   // U = 512 (power of 2)
}

// ---------------- Main kernel ----------------
// upt=2 (adjacent u-pair), TBT=8 b-rows, DC=4 d-chunk, 4-way split over D
// finishing with atomicAdd into bias-initialized out.
// Per elem: FMUL, MUFU(ex2), LOP3 (sign flip), FFMA. Loads: 0.375 LDG/elem.
static constexpr int DC      = 4;
static constexpr int TBT     = 8;
static constexpr int THREADS = 128;
static constexpr int DSPLIT  = 4;

__global__ __launch_bounds__(THREADS, 6)
void power_layer_kernel(float* __restrict__ out, int D, int U) {
    const int U2  = U >> 1;
    const int up  = blockIdx.y * THREADS + threadIdx.x;   // u-pair index
    const int b0  = blockIdx.x * TBT;
    const int nD  = D / DSPLIT;
    const int dlo = blockIdx.z * nD;

    const float4* __restrict__ pwp = g_PW4 + (size_t)dlo * U2 + up;
    const uint2*  __restrict__ omp = g_OM2 + (size_t)dlo * U2 + up;
    const float2* __restrict__ lnb = g_LN  + (size_t)b0 * D + dlo;

    float2 acc[TBT];
#pragma unroll
    for (int bb = 0; bb < TBT; bb++) acc[bb] = make_float2(0.f, 0.f);

    for (int dd = 0; dd < nD; dd += DC) {
        float4 pw[DC];
        uint2  om[DC];
#pragma unroll
        for (int j = 0; j < DC; j++) {
            pw[j] = pwp[j * U2];     // {p0,w0,p1,w1} — LDG.128
            om[j] = omp[j * U2];     // {om0,om1}     — LDG.64
        }
        pwp += DC * U2;
        omp += DC * U2;

#pragma unroll
        for (int bb = 0; bb < TBT; bb++) {
            // warp-uniform -> broadcast; float4 = 2 x {log2, negmask}
            const float4* __restrict__ ln4 =
                (const float4*)(lnb + (size_t)bb * D + dd);
            float4 lnv[DC / 2];
#pragma unroll
            for (int q = 0; q < DC / 2; q++) lnv[q] = ln4[q];

#pragma unroll
            for (int j = 0; j < DC; j++) {
                const float        lv = (j & 1) ? lnv[j >> 1].z : lnv[j >> 1].x;
                const unsigned int nm = __float_as_uint((j & 1) ? lnv[j >> 1].w
                                                                : lnv[j >> 1].y);
                float e0 = pw[j].x * lv;
                float e1 = pw[j].z * lv;
                float v0, v1;
                asm("ex2.approx.f32 %0, %1;" : "=f"(v0) : "f"(e0));
                asm("ex2.approx.f32 %0, %1;" : "=f"(v1) : "f"(e1));
                v0 = __uint_as_float(__float_as_uint(v0) ^ (om[j].x & nm));
                v1 = __uint_as_float(__float_as_uint(v1) ^ (om[j].y & nm));
                acc[bb].x = fmaf(pw[j].y, v0, acc[bb].x);
                acc[bb].y = fmaf(pw[j].w, v1, acc[bb].y);
            }
        }
    }

    float* o = out + (size_t)b0 * U + 2 * up;
#pragma unroll
    for (int bb = 0; bb < TBT; bb++) {
        atomicAdd(o + (size_t)bb * U,     acc[bb].x);
        atomicAdd(o + (size_t)bb * U + 1, acc[bb].y);
    }
}

// ---------------- Launch ----------------
extern "C" void kernel_launch(void* const* d_in, const int* in_sizes, int n_in,
                              void* d_out, int out_size) {
    const float* x    = (const float*)d_in[0];
    const float* w    = (const float*)d_in[1];
    const float* p    = (const float*)d_in[2];
    const float* bias = (const float*)d_in[3];
    float* out        = (float*)d_out;

    const int U = in_sizes[3];            // 512
    const int D = in_sizes[1] / U;        // 512
    const int B = in_sizes[0] / D;        // 1024

    const int nLN  = B * D;               // 524288
    const int nPW  = D * U / 2;           // 131072
    const int nOut = out_size;            // 524288
    int nmax = nLN > nPW ? nLN : nPW;
    if (nOut > nmax) nmax = nOut;
    prep_kernel<<<(nmax + 255) / 256, 256>>>(x, w, p, bias, out,
                                             nLN, nPW, nOut, U);

    // grid: (B/TBT, U2/THREADS, DSPLIT) = (128, 2, 4) = 1024 blocks x 4 warps
    dim3 grid(B / TBT, (U / 2) / THREADS, DSPLIT);
    power_layer_kernel<<<grid, THREADS>>>(out, D, U);
}

// round 7
// speedup vs baseline: 2.8626x; 1.1078x over previous
#include <cuda_runtime.h>
#include <cuda_bf16.h>

#define EPS 1e-9f

static constexpr int BMAX = 1024;
static constexpr int DMAX = 512;
static constexpr int UMAX = 512;

// Scratch (device globals — no allocation allowed)
__device__ float2 g_LN [BMAX * DMAX];       // {log2|x+eps|, bitcast(neg ? 0xFFFFFFFF : 0)}
__device__ float4 g_PW4[DMAX * UMAX / 2];   // per u-pair: {p0, w0, p1, w1}
__device__ uint2  g_OM2[DMAX * UMAX / 2];   // per u-pair: odd(p)?0x80000000:0

// ---------------- Fused prepass (also inits out = bias) ----------------
__global__ void prep_kernel(const float* __restrict__ x,
                            const float* __restrict__ w,
                            const float* __restrict__ p,
                            const float* __restrict__ bias,
                            float* __restrict__ out,
                            int nLN, int nPW, int nOut, int U) {
    int i = blockIdx.x * blockDim.x + threadIdx.x;
    if (i < nLN) {
        float xe = x[i] + EPS;
        float2 v;
        v.x = log2f(fabsf(xe));
        v.y = __uint_as_float((xe < 0.f) ? 0xFFFFFFFFu : 0u);
        g_LN[i] = v;
    }
    if (i < nPW) {
        const int U2 = U >> 1;
        int d  = i / U2;
        int u  = (i - d * U2) * 2;
        int idx = d * U + u;
        float p0 = p[idx],     p1 = p[idx + 1];
        float w0 = w[idx],     w1 = w[idx + 1];
        g_PW4[i] = make_float4(p0, w0, p1, w1);
        uint2 m;
        m.x = (fmodf(p0, 2.f) != 0.f) ? 0x80000000u : 0u;
        m.y = (fmodf(p1, 2.f) != 0.f) ? 0x80000000u : 0u;
        g_OM2[i] = m;
    }
    if (i < nOut) out[i] = bias[i & (U - 1)];   // U = 512 (power of 2)
}

// ---------------- Main kernel ----------------
// upt=2 (adjacent u-pair), TBT=8 b-rows, DC=4 d-chunk, 8-way split over D
// finishing with atomicAdd into bias-initialized out.
// Per elem: FMUL, MUFU(ex2), LOP3 (fused sign flip), FFMA. ~0.375 LDG/elem.
static constexpr int DC      = 4;
static constexpr int TBT     = 8;
static constexpr int THREADS = 128;
static constexpr int DSPLIT  = 8;

__global__ __launch_bounds__(THREADS, 8)
void power_layer_kernel(float* __restrict__ out, int D, int U) {
    const int U2  = U >> 1;
    const int up  = blockIdx.y * THREADS + threadIdx.x;   // u-pair index
    const int b0  = blockIdx.x * TBT;
    const int nD  = D / DSPLIT;
    const int dlo = blockIdx.z * nD;

    const float4* __restrict__ pwp = g_PW4 + (size_t)dlo * U2 + up;
    const uint2*  __restrict__ omp = g_OM2 + (size_t)dlo * U2 + up;
    const float2* __restrict__ lnb = g_LN  + (size_t)b0 * D + dlo;

    float2 acc[TBT];
#pragma unroll
    for (int bb = 0; bb < TBT; bb++) acc[bb] = make_float2(0.f, 0.f);

    for (int dd = 0; dd < nD; dd += DC) {
        float4 pw[DC];
        uint2  om[DC];
#pragma unroll
        for (int j = 0; j < DC; j++) {
            pw[j] = pwp[j * U2];     // {p0,w0,p1,w1} — LDG.128
            om[j] = omp[j * U2];     // {om0,om1}     — LDG.64
        }
        pwp += DC * U2;
        omp += DC * U2;

#pragma unroll
        for (int bb = 0; bb < TBT; bb++) {
            // warp-uniform -> broadcast; float4 = 2 x {log2, negmask}
            const float4* __restrict__ ln4 =
                (const float4*)(lnb + (size_t)bb * D + dd);
            float4 lnv[DC / 2];
#pragma unroll
            for (int q = 0; q < DC / 2; q++) lnv[q] = ln4[q];

#pragma unroll
            for (int j = 0; j < DC; j++) {
                const float        lv = (j & 1) ? lnv[j >> 1].z : lnv[j >> 1].x;
                const unsigned int nm = __float_as_uint((j & 1) ? lnv[j >> 1].w
                                                                : lnv[j >> 1].y);
                float e0 = pw[j].x * lv;
                float e1 = pw[j].z * lv;
                float v0, v1;
                asm("ex2.approx.f32 %0, %1;" : "=f"(v0) : "f"(e0));
                asm("ex2.approx.f32 %0, %1;" : "=f"(v1) : "f"(e1));
                v0 = __uint_as_float(__float_as_uint(v0) ^ (om[j].x & nm));
                v1 = __uint_as_float(__float_as_uint(v1) ^ (om[j].y & nm));
                acc[bb].x = fmaf(pw[j].y, v0, acc[bb].x);
                acc[bb].y = fmaf(pw[j].w, v1, acc[bb].y);
            }
        }
    }

    float* o = out + (size_t)b0 * U + 2 * up;
#pragma unroll
    for (int bb = 0; bb < TBT; bb++) {
        atomicAdd(o + (size_t)bb * U,     acc[bb].x);
        atomicAdd(o + (size_t)bb * U + 1, acc[bb].y);
    }
}

// ---------------- Launch ----------------
extern "C" void kernel_launch(void* const* d_in, const int* in_sizes, int n_in,
                              void* d_out, int out_size) {
    const float* x    = (const float*)d_in[0];
    const float* w    = (const float*)d_in[1];
    const float* p    = (const float*)d_in[2];
    const float* bias = (const float*)d_in[3];
    float* out        = (float*)d_out;

    const int U = in_sizes[3];            // 512
    const int D = in_sizes[1] / U;        // 512
    const int B = in_sizes[0] / D;        // 1024

    const int nLN  = B * D;               // 524288
    const int nPW  = D * U / 2;           // 131072
    const int nOut = out_size;            // 524288
    int nmax = nLN > nPW ? nLN : nPW;
    if (nOut > nmax) nmax = nOut;
    prep_kernel<<<(nmax + 255) / 256, 256>>>(x, w, p, bias, out,
                                             nLN, nPW, nOut, U);

    // grid: (B/TBT, U2/THREADS, DSPLIT) = (128, 2, 8) = 2048 blocks x 4 warps
    dim3 grid(B / TBT, (U / 2) / THREADS, DSPLIT);
    power_layer_kernel<<<grid, THREADS>>>(out, D, U);
}